// round 12
// baseline (speedup 1.0000x reference)
#include <cuda_runtime.h>

#define NN 1024
#define EPSF 1e-16f

// Static scratch (no allocation)
__device__ float g_W[NN * NN];           // (1-2*Xt)*(lam+eta*D+nu*C+mu*S)
__device__ float g_rls_part[NN * 32];    // per-(row, col-tile) partial of sum log(1-x)
__device__ float g_part[NN];             // per-row elb partial
__device__ unsigned int g_ctr;           // block-done counter, wraps to 0

__device__ __forceinline__ float wred(float v) {
#pragma unroll
    for (int o = 16; o; o >>= 1) v += __shfl_down_sync(0xffffffffu, v, o);
    return v;
}
__device__ __forceinline__ double wredd(double v) {
#pragma unroll
    for (int o = 16; o; o >>= 1) v += __shfl_down_sync(0xffffffffu, v, o);
    return v;
}
__device__ __forceinline__ float fast_tanh(float x) {
    float y;
    asm("tanh.approx.f32 %0, %1;" : "=f"(y) : "f"(x));
    return y;
}

// ---------------------------------------------------------------------------
// Kernel 0: prep — rls partials + fused W = (1-2*Xt)*(lam+eta*D+nu*C+mu*S).
// Tiled like a transpose: block (bx,by) loads X[by..by+31][bx..bx+31] and
// produces W rows i in [bx..bx+31], cols j in [by..by+31].
// ---------------------------------------------------------------------------
__global__ void k_prep(const float* __restrict__ X,
                       const float* __restrict__ C,
                       const float* __restrict__ D,
                       const float* __restrict__ S,
                       const float* __restrict__ LAM, const float* __restrict__ ETA,
                       const float* __restrict__ NU,  const float* __restrict__ MU) {
    __shared__ float tile[32][33];
    int bx = blockIdx.x * 32, by = blockIdx.y * 32;
    int tx = threadIdx.x, ty = threadIdx.y;
    float lam = LAM[0], eta = ETA[0], nu = NU[0], mu = MU[0];
#pragma unroll
    for (int r = 0; r < 32; r += 8) {
        float x = X[(by + ty + r) * NN + bx + tx];
        tile[ty + r][tx] = x;
        float lx = __logf(1.f - x + EPSF);
        float s = wred(lx);
        if (tx == 0) g_rls_part[(by + ty + r) * 32 + blockIdx.x] = s;
    }
    __syncthreads();
#pragma unroll
    for (int r = 0; r < 32; r += 8) {
        int i = bx + ty + r;          // W row
        int j = by + tx;              // W col
        size_t e = (size_t)i * NN + j;
        float xt = tile[tx][ty + r];  // X[j][i]
        float pr = lam + eta*D[e] + nu*C[e] + mu*S[e];
        g_W[e] = (1.f - 2.f*xt) * pr;
    }
}

// ---------------------------------------------------------------------------
// Kernel 1: fused main. Fast path (rls < -125 => exp(rls-lx) and exp(rls)
// both underflow to exactly 0 in fp32, matching the reference). All pair/xt
// usage flows through W. Slow path full-fidelity (modulo fp reassociation).
// ---------------------------------------------------------------------------
__global__ void __launch_bounds__(512, 3) k_main(
    const float* __restrict__ X,
    const float* __restrict__ Mk,
    const float* __restrict__ Tt,
    const float* __restrict__ B0, const float* __restrict__ B1, const float* __restrict__ B2,
    const float* __restrict__ KAP,
    const int* __restrict__ Iij,     // (N,N,6)
    const int* __restrict__ IijF,    // (N,N,6)
    const int* __restrict__ IijT,    // (N,N,6,5)
    const int* __restrict__ IiT,     // (N,21,2)
    float* __restrict__ out)
{
    int i = blockIdx.x, tid = threadIdx.x;
    __shared__ float  xs[NN];        // x (both paths)
    __shared__ float  xxs[NN];       // x/(1-x+eps)  (slow path only)
    __shared__ float  redC[16];
    __shared__ double redD[16];
    __shared__ float  s_spl;
    __shared__ bool   s_last;

    const float* rowX = X + (size_t)i * NN;
    const int4*  pIJ  = (const int4*)(Iij + (size_t)i * NN * 6);
    const int p  = tid;              // pair index 0..511
    const int j0 = 2 * p;
    const int lane = tid & 31;

    // ---- prefetch the dependency-chain head: index loads (DRAM) ----
    int4 q0 = pIJ[p*3+0], q1 = pIJ[p*3+1], q2 = pIJ[p*3+2];

    // ---- row load + smem publish (one STS.64) ----
    float2 xq = ((const float2*)rowX)[tid];
    *(float2*)(xs + j0) = xq;

    // rls: every warp butterflies the same 32-float partial line.
    float rls = g_rls_part[i * 32 + lane];
#pragma unroll
    for (int o = 16; o; o >>= 1) rls += __shfl_xor_sync(0xffffffffu, rls, o);

    __syncthreads();

    // ---- scalars ----
    float t  = Tt[0];
    float k0 = KAP[0], k1 = KAP[1], k2 = KAP[2], k3 = KAP[3], k4 = KAP[4], k5 = KAP[5];
    float Ksum = ((k0 + k1) + (k2 + k3)) + (k4 + k5);
    float invt  = __fdividef(1.f, t);
    float hinvt = 0.5f * invt;

    const float2* pW = (const float2*)(g_W + (size_t)i * NN);
    const float2* pM = (const float2*)(Mk  + (size_t)i * NN);
    float* outg = out + 1 + (size_t)i * NN;

    float2 Wv = pW[p], Mv = pM[p];

    float acc = 0.f;
    float elbrow = 0.f;
    bool fastpath = rls < -125.0f;

    if (fastpath) {
        // ===== tmp0 == 0 and exp(rls) == 0 =====
        // element 0
        {
            float skap = k0*xs[q0.x] + k1*xs[q0.y] + k2*xs[q0.z]
                       + k3*xs[q0.w] + k4*xs[q1.x] + k5*xs[q1.y];
            float xv = xq.x;
            float m  = Mv.x;
            float u  = Wv.x + (Ksum - 2.f*skap);
            float gm = fmaf(100.f, m, -100.f) - 2.f*u;
            __stcs(outg + j0, fmaf(0.5f, fast_tanh(gm * hinvt), 0.5f));
            float x_ = 1.f - xv + EPSF;
            float ent = xv*__logf(xv + EPSF) + x_*__logf(x_);
            acc += m * (fmaf(1.f - 2.f*xv, u, -t*ent));
        }
        // element 1
        {
            float skap = k0*xs[q1.z] + k1*xs[q1.w] + k2*xs[q2.x]
                       + k3*xs[q2.y] + k4*xs[q2.z] + k5*xs[q2.w];
            float xv = xq.y;
            float m  = Mv.y;
            float u  = Wv.y + (Ksum - 2.f*skap);
            float gm = fmaf(100.f, m, -100.f) - 2.f*u;
            __stcs(outg + j0 + 1, fmaf(0.5f, fast_tanh(gm * hinvt), 0.5f));
            float x_ = 1.f - xv + EPSF;
            float ent = xv*__logf(xv + EPSF) + x_*__logf(x_);
            acc += m * (fmaf(1.f - 2.f*xv, u, -t*ent));
        }
    } else {
        // ===== full slow path (never taken for bench data, kept for rigor) =====
        float x_0 = 1.f - xq.x + EPSF;
        float x_1 = 1.f - xq.y + EPSF;
        float lx0 = __logf(x_0);
        float lx1 = __logf(x_1);
        xxs[j0]     = __fdividef(xq.x, x_0);
        xxs[j0 + 1] = __fdividef(xq.y, x_1);
        __syncthreads();

        // xxsum reduction
        float xxl = xxs[j0] + xxs[j0 + 1];
        float wb = wred(xxl);
        if (lane == 0) redC[tid >> 5] = wb;
        __syncthreads();
        float xxsumT = 0.f;
#pragma unroll
        for (int w = 0; w < 16; w++) xxsumT += redC[w];

        // iT: sum of 21 products (warp 0)
        if (tid < 32) {
            float spl = 0.f;
            if (tid < 21) {
                int ka = IiT[((size_t)i * 21 + tid) * 2 + 0];
                int kb = IiT[((size_t)i * 21 + tid) * 2 + 1];
                spl = xxs[ka] * xxs[kb];
            }
            spl = wred(spl);
            if (tid == 0) s_spl = spl;
        }
        __syncthreads();

        float b0v = B0[0], b1v = B1[0], b2v = B2[0];
        float b1b0 = b1v - b0v, b2b1 = b2v - b1v;
        elbrow = (b0v + xxsumT*b1v + s_spl*b2v) * __expf(rls);

        const int4* pF = (const int4*)(IijF + (size_t)i * NN * 6);
        const int4* pT = (const int4*)(IijT + (size_t)i * NN * 30);
        int4 r0 = pF[p*3+0], r1 = pF[p*3+1], r2 = pF[p*3+2];

        // element 0
        {
            int4 u0 = pT[p*15+0], u1 = pT[p*15+1], u2 = pT[p*15+2], u3 = pT[p*15+3];
            int4 u4 = pT[p*15+4], u5 = pT[p*15+5], u6 = pT[p*15+6], u7 = pT[p*15+7];
            float locUp0 = ((xxs[q0.x] + xxs[q0.y]) + (xxs[q0.z] + xxs[q0.w]))
                         + (xxs[q1.x] + xxs[q1.y]);
            float skap = k0*xs[q0.x] + k1*xs[q0.y] + k2*xs[q0.z]
                       + k3*xs[q0.w] + k4*xs[q1.x] + k5*xs[q1.y];
            float f0 = xxs[r0.x], f1 = xxs[r0.y], f2 = xxs[r0.z],
                  f3 = xxs[r0.w], f4 = xxs[r1.x], f5 = xxs[r1.y];
            float s0 = xxs[u0.x]+xxs[u0.y]+xxs[u0.z]+xxs[u0.w]+xxs[u1.x];
            float s1 = xxs[u1.y]+xxs[u1.z]+xxs[u1.w]+xxs[u2.x]+xxs[u2.y];
            float s2 = xxs[u2.z]+xxs[u2.w]+xxs[u3.x]+xxs[u3.y]+xxs[u3.z];
            float s3 = xxs[u3.w]+xxs[u4.x]+xxs[u4.y]+xxs[u4.z]+xxs[u4.w];
            float s4 = xxs[u5.x]+xxs[u5.y]+xxs[u5.z]+xxs[u5.w]+xxs[u6.x];
            float s5 = xxs[u6.y]+xxs[u6.z]+xxs[u6.w]+xxs[u7.x]+xxs[u7.y];
            float locUp1 = f0*s0 + f1*s1 + f2*s2 + f3*s3 + f4*s4 + f5*s5;

            float xv = xq.x;
            float tmp0 = __expf(rls - lx0);
            float m  = Mv.x;
            float u  = Wv.x + (Ksum - 2.f*skap);
            float gm = (b1b0 + b2b1*locUp0 - b2v*locUp1)*tmp0
                     + fmaf(100.f, m, -100.f) - 2.f*u;
            outg[j0] = __fdividef(1.f, 1.f + __expf(-gm*invt));
            float ent = xv*__logf(xv + EPSF) + x_0*lx0;
            acc += m * (fmaf(1.f - 2.f*xv, u, -t*ent));
        }
        // element 1
        {
            int4 u7  = pT[p*15+7];
            int4 u8  = pT[p*15+8],  u9  = pT[p*15+9],  u10 = pT[p*15+10];
            int4 u11 = pT[p*15+11], u12 = pT[p*15+12], u13 = pT[p*15+13], u14 = pT[p*15+14];
            float locUp0 = ((xxs[q1.z] + xxs[q1.w]) + (xxs[q2.x] + xxs[q2.y]))
                         + (xxs[q2.z] + xxs[q2.w]);
            float skap = k0*xs[q1.z] + k1*xs[q1.w] + k2*xs[q2.x]
                       + k3*xs[q2.y] + k4*xs[q2.z] + k5*xs[q2.w];
            float f0 = xxs[r1.z], f1 = xxs[r1.w], f2 = xxs[r2.x],
                  f3 = xxs[r2.y], f4 = xxs[r2.z], f5 = xxs[r2.w];
            float s0 = xxs[u7.z]+xxs[u7.w]+xxs[u8.x]+xxs[u8.y]+xxs[u8.z];
            float s1 = xxs[u8.w]+xxs[u9.x]+xxs[u9.y]+xxs[u9.z]+xxs[u9.w];
            float s2 = xxs[u10.x]+xxs[u10.y]+xxs[u10.z]+xxs[u10.w]+xxs[u11.x];
            float s3 = xxs[u11.y]+xxs[u11.z]+xxs[u11.w]+xxs[u12.x]+xxs[u12.y];
            float s4 = xxs[u12.z]+xxs[u12.w]+xxs[u13.x]+xxs[u13.y]+xxs[u13.z];
            float s5 = xxs[u13.w]+xxs[u14.x]+xxs[u14.y]+xxs[u14.z]+xxs[u14.w];
            float locUp1 = f0*s0 + f1*s1 + f2*s2 + f3*s3 + f4*s4 + f5*s5;

            float xv = xq.y;
            float tmp0 = __expf(rls - lx1);
            float m  = Mv.y;
            float u  = Wv.y + (Ksum - 2.f*skap);
            float gm = (b1b0 + b2b1*locUp0 - b2v*locUp1)*tmp0
                     + fmaf(100.f, m, -100.f) - 2.f*u;
            outg[j0 + 1] = __fdividef(1.f, 1.f + __expf(-gm*invt));
            float ent = xv*__logf(xv + EPSF) + x_1*lx1;
            acc += m * (fmaf(1.f - 2.f*xv, u, -t*ent));
        }
        __syncthreads();
    }

    // ---- block reduction of acc; emit per-row partial ----
    float ar = wred(acc);
    if (lane == 0) redC[tid >> 5] = ar;
    __syncthreads();
    if (tid == 0) {
        float tot = 0.f;
#pragma unroll
        for (int w = 0; w < 16; w++) tot += redC[w];
        g_part[i] = tot + elbrow;
        __threadfence();
        unsigned int old = atomicInc(&g_ctr, NN - 1);   // wraps to 0 after NN incs
        s_last = (old == NN - 1);
    }
    __syncthreads();

    // ---- last block: deterministic final sum in double ----
    if (s_last) {
        double dv = (double)g_part[tid] + (double)g_part[tid + 512];
        double dr = wredd(dv);
        if (lane == 0) redD[tid >> 5] = dr;
        __syncthreads();
        if (tid == 0) {
            double tt = 0.0;
#pragma unroll
            for (int w = 0; w < 16; w++) tt += redD[w];
            out[0] = (float)tt;
        }
    }
}

// ---------------------------------------------------------------------------
extern "C" void kernel_launch(void* const* d_in, const int* in_sizes, int n_in,
                              void* d_out, int out_size) {
    const float* X    = (const float*)d_in[0];
    const float* T    = (const float*)d_in[1];
    const float* C    = (const float*)d_in[2];
    const float* D    = (const float*)d_in[3];
    const float* S    = (const float*)d_in[4];
    const float* Mk   = (const float*)d_in[5];
    const float* b0   = (const float*)d_in[6];
    const float* b1   = (const float*)d_in[7];
    const float* b2   = (const float*)d_in[8];
    const float* lam  = (const float*)d_in[9];
    const float* eta  = (const float*)d_in[10];
    const float* nu   = (const float*)d_in[11];
    const float* mu   = (const float*)d_in[12];
    const float* kap  = (const float*)d_in[13];
    const int*   iij  = (const int*)d_in[14];
    const int*   iijF = (const int*)d_in[15];
    const int*   iijT = (const int*)d_in[16];
    const int*   iiT  = (const int*)d_in[17];
    float* out = (float*)d_out;

    k_prep<<<dim3(32, 32), dim3(32, 8)>>>(X, C, D, S, lam, eta, nu, mu);
    k_main<<<NN, 512>>>(X, Mk, T, b0, b1, b2, kap,
                        iij, iijF, iijT, iiT, out);
}

// round 13
// speedup vs baseline: 1.0030x; 1.0030x over previous
#include <cuda_runtime.h>

#define NN 1024
#define EPSF 1e-16f

// Static scratch (no allocation)
__device__ float g_Xt[NN * NN];          // X transpose
__device__ float g_rls_part[NN * 32];    // per-(row, col-tile) partial of sum log(1-x)
__device__ float g_part[NN];             // per-row elb partial
__device__ unsigned int g_ctr;           // block-done counter, wraps to 0

__device__ __forceinline__ float wred(float v) {
#pragma unroll
    for (int o = 16; o; o >>= 1) v += __shfl_down_sync(0xffffffffu, v, o);
    return v;
}
__device__ __forceinline__ double wredd(double v) {
#pragma unroll
    for (int o = 16; o; o >>= 1) v += __shfl_down_sync(0xffffffffu, v, o);
    return v;
}

// ---------------------------------------------------------------------------
// Kernel 0: tiled transpose X -> g_Xt, plus deterministic per-(row,tile)
// partials of sum_j log(1-x+eps) into g_rls_part.
// ---------------------------------------------------------------------------
__global__ void k_transpose(const float* __restrict__ X) {
    __shared__ float tile[32][33];
    int bx = blockIdx.x * 32, by = blockIdx.y * 32;
    int tx = threadIdx.x, ty = threadIdx.y;
#pragma unroll
    for (int r = 0; r < 32; r += 8) {
        float x = X[(by + ty + r) * NN + bx + tx];
        tile[ty + r][tx] = x;
        float lx = __logf(1.f - x + EPSF);
        float s = wred(lx);
        if (tx == 0) g_rls_part[(by + ty + r) * 32 + blockIdx.x] = s;
    }
    __syncthreads();
#pragma unroll
    for (int r = 0; r < 32; r += 8)
        g_Xt[(bx + ty + r) * NN + by + tx] = tile[tx][ty + r];
}

// ---------------------------------------------------------------------------
// Kernel 1: fused main. Fast path (rls < -125 => exp(rls-lx) and exp(rls)
// both underflow to exactly 0 in fp32, as in the reference). Index block is
// staged through shared memory with coalesced LDG.128 (the direct per-thread
// pattern has a 48B lane stride = 3x L1 wavefronts); the 48B-stride LDS.128
// readback is bank-conflict-free.
// ---------------------------------------------------------------------------
__global__ void __launch_bounds__(512, 3) k_main(
    const float* __restrict__ X,
    const float* __restrict__ C,
    const float* __restrict__ D,
    const float* __restrict__ S,
    const float* __restrict__ Mk,
    const float* __restrict__ Tt,
    const float* __restrict__ B0, const float* __restrict__ B1, const float* __restrict__ B2,
    const float* __restrict__ LAM, const float* __restrict__ ETA,
    const float* __restrict__ NU, const float* __restrict__ MU,
    const float* __restrict__ KAP,
    const int* __restrict__ Iij,     // (N,N,6)
    const int* __restrict__ IijF,    // (N,N,6)
    const int* __restrict__ IijT,    // (N,N,6,5)
    const int* __restrict__ IiT,     // (N,21,2)
    float* __restrict__ out)
{
    int i = blockIdx.x, tid = threadIdx.x;
    __shared__ int4   sIdx[1536];    // staged Iij row: 512 pairs x 3 int4
    __shared__ float  xs[NN];        // x (both paths)
    __shared__ float  xxs[NN];       // x/(1-x+eps)  (slow path only)
    __shared__ float  redC[16];
    __shared__ double redD[16];
    __shared__ float  s_spl;
    __shared__ bool   s_last;

    const float* rowX = X + (size_t)i * NN;
    const int4*  pIJ  = (const int4*)(Iij + (size_t)i * NN * 6);
    const int p  = tid;              // pair index 0..511
    const int j0 = 2 * p;
    const int lane = tid & 31;

    // ---- coalesced index staging (adjacent threads -> adjacent int4) ----
#pragma unroll
    for (int k = 0; k < 3; k++)
        sIdx[tid + k * 512] = pIJ[tid + k * 512];

    // ---- row load + smem publish (one STS.64) ----
    float2 xq = ((const float2*)rowX)[tid];
    *(float2*)(xs + j0) = xq;

    // rls: every warp butterflies the same 32-float partial line.
    float rls = g_rls_part[i * 32 + lane];
#pragma unroll
    for (int o = 16; o; o >>= 1) rls += __shfl_xor_sync(0xffffffffu, rls, o);

    __syncthreads();

    // own indices from smem (48B-stride LDS.128: conflict-free)
    int4 q0 = sIdx[3 * p], q1 = sIdx[3 * p + 1], q2 = sIdx[3 * p + 2];

    // ---- scalars ----
    float t   = Tt[0];
    float lam = LAM[0], eta = ETA[0], nu = NU[0], mu = MU[0];
    float k0 = KAP[0], k1 = KAP[1], k2 = KAP[2], k3 = KAP[3], k4 = KAP[4], k5 = KAP[5];
    float Ksum = ((k0 + k1) + (k2 + k3)) + (k4 + k5);
    float twoK = 2.f * Ksum;
    float invt = __fdividef(1.f, t);

    const float2* pC  = (const float2*)(C    + (size_t)i * NN);
    const float2* pD  = (const float2*)(D    + (size_t)i * NN);
    const float2* pS  = (const float2*)(S    + (size_t)i * NN);
    const float2* pM  = (const float2*)(Mk   + (size_t)i * NN);
    const float2* pXt = (const float2*)(g_Xt + (size_t)i * NN);
    float* outg = out + 1 + (size_t)i * NN;

    float2 Cv = pC[p], Dv = pD[p], Sv = pS[p], Mv = pM[p], Xtv = pXt[p];

    float x_0 = 1.f - xq.x + EPSF;
    float x_1 = 1.f - xq.y + EPSF;
    float lx0 = __logf(x_0);
    float lx1 = __logf(x_1);

    float acc = 0.f;
    float elbrow = 0.f;
    bool fastpath = rls < -125.0f;

    if (fastpath) {
        // ===== tmp0 == 0 and exp(rls) == 0: only skap/pair/entropy remain =====
        // element 0
        {
            float skap = k0*xs[q0.x] + k1*xs[q0.y] + k2*xs[q0.z]
                       + k3*xs[q0.w] + k4*xs[q1.x] + k5*xs[q1.y];
            float xv = xq.x, xt = Xtv.x;
            float pr = lam + eta*Dv.x + nu*Cv.x + mu*Sv.x;
            float m  = Mv.x;
            float gm = (4.f*xt - 2.f)*pr + 100.f*(m - 1.f) + (4.f*skap - twoK);
            __stcs(outg + j0, __fdividef(1.f, 1.f + __expf(-gm*invt)));
            float ent = xv*__logf(xv + EPSF) + x_0*lx0;
            acc += m*( pr*(1.f + 4.f*xv*xt - 2.f*(xv + xt))
                     + (1.f - 2.f*xv)*(Ksum - 2.f*skap) - t*ent );
        }
        // element 1
        {
            float skap = k0*xs[q1.z] + k1*xs[q1.w] + k2*xs[q2.x]
                       + k3*xs[q2.y] + k4*xs[q2.z] + k5*xs[q2.w];
            float xv = xq.y, xt = Xtv.y;
            float pr = lam + eta*Dv.y + nu*Cv.y + mu*Sv.y;
            float m  = Mv.y;
            float gm = (4.f*xt - 2.f)*pr + 100.f*(m - 1.f) + (4.f*skap - twoK);
            __stcs(outg + j0 + 1, __fdividef(1.f, 1.f + __expf(-gm*invt)));
            float ent = xv*__logf(xv + EPSF) + x_1*lx1;
            acc += m*( pr*(1.f + 4.f*xv*xt - 2.f*(xv + xt))
                     + (1.f - 2.f*xv)*(Ksum - 2.f*skap) - t*ent );
        }
    } else {
        // ===== full slow path (never taken for bench data, kept for rigor) =====
        xxs[j0]     = __fdividef(xq.x, x_0);
        xxs[j0 + 1] = __fdividef(xq.y, x_1);
        __syncthreads();

        // xxsum reduction
        float xxl = xxs[j0] + xxs[j0 + 1];
        float wb = wred(xxl);
        if (lane == 0) redC[tid >> 5] = wb;
        __syncthreads();
        float xxsumT = 0.f;
#pragma unroll
        for (int w = 0; w < 16; w++) xxsumT += redC[w];

        // iT: sum of 21 products (warp 0)
        if (tid < 32) {
            float spl = 0.f;
            if (tid < 21) {
                int ka = IiT[((size_t)i * 21 + tid) * 2 + 0];
                int kb = IiT[((size_t)i * 21 + tid) * 2 + 1];
                spl = xxs[ka] * xxs[kb];
            }
            spl = wred(spl);
            if (tid == 0) s_spl = spl;
        }
        __syncthreads();

        float b0v = B0[0], b1v = B1[0], b2v = B2[0];
        float b1b0 = b1v - b0v, b2b1 = b2v - b1v;
        elbrow = (b0v + xxsumT*b1v + s_spl*b2v) * __expf(rls);

        const int4* pF = (const int4*)(IijF + (size_t)i * NN * 6);
        const int4* pT = (const int4*)(IijT + (size_t)i * NN * 30);
        int4 r0 = pF[p*3+0], r1 = pF[p*3+1], r2 = pF[p*3+2];

        // element 0
        {
            int4 u0 = pT[p*15+0], u1 = pT[p*15+1], u2 = pT[p*15+2], u3 = pT[p*15+3];
            int4 u4 = pT[p*15+4], u5 = pT[p*15+5], u6 = pT[p*15+6], u7 = pT[p*15+7];
            float locUp0 = ((xxs[q0.x] + xxs[q0.y]) + (xxs[q0.z] + xxs[q0.w]))
                         + (xxs[q1.x] + xxs[q1.y]);
            float skap = k0*xs[q0.x] + k1*xs[q0.y] + k2*xs[q0.z]
                       + k3*xs[q0.w] + k4*xs[q1.x] + k5*xs[q1.y];
            float f0 = xxs[r0.x], f1 = xxs[r0.y], f2 = xxs[r0.z],
                  f3 = xxs[r0.w], f4 = xxs[r1.x], f5 = xxs[r1.y];
            float s0 = xxs[u0.x]+xxs[u0.y]+xxs[u0.z]+xxs[u0.w]+xxs[u1.x];
            float s1 = xxs[u1.y]+xxs[u1.z]+xxs[u1.w]+xxs[u2.x]+xxs[u2.y];
            float s2 = xxs[u2.z]+xxs[u2.w]+xxs[u3.x]+xxs[u3.y]+xxs[u3.z];
            float s3 = xxs[u3.w]+xxs[u4.x]+xxs[u4.y]+xxs[u4.z]+xxs[u4.w];
            float s4 = xxs[u5.x]+xxs[u5.y]+xxs[u5.z]+xxs[u5.w]+xxs[u6.x];
            float s5 = xxs[u6.y]+xxs[u6.z]+xxs[u6.w]+xxs[u7.x]+xxs[u7.y];
            float locUp1 = f0*s0 + f1*s1 + f2*s2 + f3*s3 + f4*s4 + f5*s5;

            float xv = xq.x, xt = Xtv.x;
            float tmp0 = __expf(rls - lx0);
            float pr = lam + eta*Dv.x + nu*Cv.x + mu*Sv.x;
            float m  = Mv.x;
            float gm = (b1b0 + b2b1*locUp0 - b2v*locUp1)*tmp0
                     + (4.f*xt - 2.f)*pr + 100.f*(m - 1.f) + (4.f*skap - twoK);
            outg[j0] = __fdividef(1.f, 1.f + __expf(-gm*invt));
            float ent = xv*__logf(xv + EPSF) + x_0*lx0;
            acc += m*( pr*(1.f + 4.f*xv*xt - 2.f*(xv + xt))
                     + (1.f - 2.f*xv)*(Ksum - 2.f*skap) - t*ent );
        }
        // element 1
        {
            int4 u7  = pT[p*15+7];
            int4 u8  = pT[p*15+8],  u9  = pT[p*15+9],  u10 = pT[p*15+10];
            int4 u11 = pT[p*15+11], u12 = pT[p*15+12], u13 = pT[p*15+13], u14 = pT[p*15+14];
            float locUp0 = ((xxs[q1.z] + xxs[q1.w]) + (xxs[q2.x] + xxs[q2.y]))
                         + (xxs[q2.z] + xxs[q2.w]);
            float skap = k0*xs[q1.z] + k1*xs[q1.w] + k2*xs[q2.x]
                       + k3*xs[q2.y] + k4*xs[q2.z] + k5*xs[q2.w];
            float f0 = xxs[r1.z], f1 = xxs[r1.w], f2 = xxs[r2.x],
                  f3 = xxs[r2.y], f4 = xxs[r2.z], f5 = xxs[r2.w];
            float s0 = xxs[u7.z]+xxs[u7.w]+xxs[u8.x]+xxs[u8.y]+xxs[u8.z];
            float s1 = xxs[u8.w]+xxs[u9.x]+xxs[u9.y]+xxs[u9.z]+xxs[u9.w];
            float s2 = xxs[u10.x]+xxs[u10.y]+xxs[u10.z]+xxs[u10.w]+xxs[u11.x];
            float s3 = xxs[u11.y]+xxs[u11.z]+xxs[u11.w]+xxs[u12.x]+xxs[u12.y];
            float s4 = xxs[u12.z]+xxs[u12.w]+xxs[u13.x]+xxs[u13.y]+xxs[u13.z];
            float s5 = xxs[u13.w]+xxs[u14.x]+xxs[u14.y]+xxs[u14.z]+xxs[u14.w];
            float locUp1 = f0*s0 + f1*s1 + f2*s2 + f3*s3 + f4*s4 + f5*s5;

            float xv = xq.y, xt = Xtv.y;
            float tmp0 = __expf(rls - lx1);
            float pr = lam + eta*Dv.y + nu*Cv.y + mu*Sv.y;
            float m  = Mv.y;
            float gm = (b1b0 + b2b1*locUp0 - b2v*locUp1)*tmp0
                     + (4.f*xt - 2.f)*pr + 100.f*(m - 1.f) + (4.f*skap - twoK);
            outg[j0 + 1] = __fdividef(1.f, 1.f + __expf(-gm*invt));
            float ent = xv*__logf(xv + EPSF) + x_1*lx1;
            acc += m*( pr*(1.f + 4.f*xv*xt - 2.f*(xv + xt))
                     + (1.f - 2.f*xv)*(Ksum - 2.f*skap) - t*ent );
        }
        __syncthreads();
    }

    // ---- block reduction of acc; emit per-row partial ----
    float ar = wred(acc);
    if (lane == 0) redC[tid >> 5] = ar;
    __syncthreads();
    if (tid == 0) {
        float tot = 0.f;
#pragma unroll
        for (int w = 0; w < 16; w++) tot += redC[w];
        g_part[i] = tot + elbrow;
        __threadfence();
        unsigned int old = atomicInc(&g_ctr, NN - 1);   // wraps to 0 after NN incs
        s_last = (old == NN - 1);
    }
    __syncthreads();

    // ---- last block: deterministic final sum in double ----
    if (s_last) {
        double dv = (double)g_part[tid] + (double)g_part[tid + 512];
        double dr = wredd(dv);
        if (lane == 0) redD[tid >> 5] = dr;
        __syncthreads();
        if (tid == 0) {
            double tt = 0.0;
#pragma unroll
            for (int w = 0; w < 16; w++) tt += redD[w];
            out[0] = (float)tt;
        }
    }
}

// ---------------------------------------------------------------------------
extern "C" void kernel_launch(void* const* d_in, const int* in_sizes, int n_in,
                              void* d_out, int out_size) {
    const float* X    = (const float*)d_in[0];
    const float* T    = (const float*)d_in[1];
    const float* C    = (const float*)d_in[2];
    const float* D    = (const float*)d_in[3];
    const float* S    = (const float*)d_in[4];
    const float* Mk   = (const float*)d_in[5];
    const float* b0   = (const float*)d_in[6];
    const float* b1   = (const float*)d_in[7];
    const float* b2   = (const float*)d_in[8];
    const float* lam  = (const float*)d_in[9];
    const float* eta  = (const float*)d_in[10];
    const float* nu   = (const float*)d_in[11];
    const float* mu   = (const float*)d_in[12];
    const float* kap  = (const float*)d_in[13];
    const int*   iij  = (const int*)d_in[14];
    const int*   iijF = (const int*)d_in[15];
    const int*   iijT = (const int*)d_in[16];
    const int*   iiT  = (const int*)d_in[17];
    float* out = (float*)d_out;

    k_transpose<<<dim3(32, 32), dim3(32, 8)>>>(X);
    k_main<<<NN, 512>>>(X, C, D, S, Mk, T, b0, b1, b2, lam, eta, nu, mu, kap,
                        iij, iijF, iijT, iiT, out);
}

// round 14
// speedup vs baseline: 1.1233x; 1.1199x over previous
#include <cuda_runtime.h>

#define NN 1024
#define EPSF 1e-16f
#define GRID 256
#define ROWS_PER_BLK 4

// Static scratch (no allocation)
__device__ float g_W[NN * NN];           // (1-2*Xt)*(lam+eta*D+nu*C+mu*S)
__device__ float g_rls_part[NN * 32];    // per-(row, col-tile) partial of sum log(1-x)
__device__ float g_part[GRID];           // per-block elb partial
__device__ unsigned int g_ctr;           // block-done counter, wraps to 0

__device__ __forceinline__ float wred(float v) {
#pragma unroll
    for (int o = 16; o; o >>= 1) v += __shfl_down_sync(0xffffffffu, v, o);
    return v;
}
__device__ __forceinline__ double wredd(double v) {
#pragma unroll
    for (int o = 16; o; o >>= 1) v += __shfl_down_sync(0xffffffffu, v, o);
    return v;
}

// ---------------------------------------------------------------------------
// Kernel 0: prep — rls partials + fused W = (1-2*Xt)*(lam+eta*D+nu*C+mu*S).
// ---------------------------------------------------------------------------
__global__ void k_prep(const float* __restrict__ X,
                       const float* __restrict__ C,
                       const float* __restrict__ D,
                       const float* __restrict__ S,
                       const float* __restrict__ LAM, const float* __restrict__ ETA,
                       const float* __restrict__ NU,  const float* __restrict__ MU) {
    __shared__ float tile[32][33];
    int bx = blockIdx.x * 32, by = blockIdx.y * 32;
    int tx = threadIdx.x, ty = threadIdx.y;
    float lam = LAM[0], eta = ETA[0], nu = NU[0], mu = MU[0];
#pragma unroll
    for (int r = 0; r < 32; r += 8) {
        float x = X[(by + ty + r) * NN + bx + tx];
        tile[ty + r][tx] = x;
        float lx = __logf(1.f - x + EPSF);
        float s = wred(lx);
        if (tx == 0) g_rls_part[(by + ty + r) * 32 + blockIdx.x] = s;
    }
    __syncthreads();
#pragma unroll
    for (int r = 0; r < 32; r += 8) {
        int i = bx + ty + r;          // W row
        int j = by + tx;              // W col
        size_t e = (size_t)i * NN + j;
        float xt = tile[tx][ty + r];  // X[j][i]
        float pr = lam + eta*D[e] + nu*C[e] + mu*S[e];
        g_W[e] = (1.f - 2.f*xt) * pr;
    }
}

// ---------------------------------------------------------------------------
// Kernel 1: persistent single-wave main. 256 blocks x 4 rows, software-
// pipelined: row k+1's DRAM loads issue before row k's compute. Fast path
// (rls < -125 => exp(rls-lx) and exp(rls) underflow to exactly 0 in fp32,
// matching the reference); slow path full-fidelity per row.
// ---------------------------------------------------------------------------
__global__ void __launch_bounds__(512, 2) k_main(
    const float* __restrict__ X,
    const float* __restrict__ Mk,
    const float* __restrict__ Tt,
    const float* __restrict__ B0, const float* __restrict__ B1, const float* __restrict__ B2,
    const float* __restrict__ KAP,
    const int* __restrict__ Iij,     // (N,N,6)
    const int* __restrict__ IijF,    // (N,N,6)
    const int* __restrict__ IijT,    // (N,N,6,5)
    const int* __restrict__ IiT,     // (N,21,2)
    float* __restrict__ out)
{
    const int bid = blockIdx.x, tid = threadIdx.x;
    const int ibase = bid * ROWS_PER_BLK;
    __shared__ float  xs[2][NN];     // double-buffered row of x
    __shared__ float  xxs[NN];       // slow path only
    __shared__ float  redC[16];
    __shared__ double redD[16];
    __shared__ float  s_spl;
    __shared__ bool   s_last;

    const int p  = tid;              // pair index 0..511
    const int j0 = 2 * p;
    const int lane = tid & 31;

    // ---- scalars ----
    float t  = Tt[0];
    float k0 = KAP[0], k1 = KAP[1], k2 = KAP[2], k3 = KAP[3], k4 = KAP[4], k5 = KAP[5];
    float Ksum = ((k0 + k1) + (k2 + k3)) + (k4 + k5);
    float invt = __fdividef(1.f, t);

    // ---- prologue: row 0 loads ----
    int4 cq0, cq1, cq2; float2 cW, cM, cx; float crl;
    {
        const int4* pIJ = (const int4*)(Iij + (size_t)ibase * NN * 6);
        cq0 = pIJ[3*p]; cq1 = pIJ[3*p+1]; cq2 = pIJ[3*p+2];
        cW  = ((const float2*)(g_W + (size_t)ibase * NN))[p];
        cM  = ((const float2*)(Mk  + (size_t)ibase * NN))[p];
        cx  = ((const float2*)(X   + (size_t)ibase * NN))[p];
        crl = g_rls_part[ibase * 32 + lane];
    }
    *(float2*)(&xs[0][j0]) = cx;

    float acc = 0.f;
    float elb_extra = 0.f;

#pragma unroll
    for (int k = 0; k < ROWS_PER_BLK; k++) {
        const int i = ibase + k;

        // ---- issue next row's loads (hidden behind this row's compute) ----
        int4 nq0, nq1, nq2; float2 nW, nM, nx; float nrl;
        if (k + 1 < ROWS_PER_BLK) {
            const int i2 = i + 1;
            const int4* pIJ = (const int4*)(Iij + (size_t)i2 * NN * 6);
            nq0 = pIJ[3*p]; nq1 = pIJ[3*p+1]; nq2 = pIJ[3*p+2];
            nW  = ((const float2*)(g_W + (size_t)i2 * NN))[p];
            nM  = ((const float2*)(Mk  + (size_t)i2 * NN))[p];
            nx  = ((const float2*)(X   + (size_t)i2 * NN))[p];
            nrl = g_rls_part[i2 * 32 + lane];
        }

        // rls for current row: butterfly (all lanes get total)
        float rls = crl;
#pragma unroll
        for (int o = 16; o; o >>= 1) rls += __shfl_xor_sync(0xffffffffu, rls, o);

        __syncthreads();              // xs[k&1] published (and prev readers done)

        const float* xr = xs[k & 1];
        float* outg = out + 1 + (size_t)i * NN;
        bool fastpath = rls < -125.0f;   // block-uniform

        if (fastpath) {
            // ===== tmp0 == 0 and exp(rls) == 0 =====
            // element 0
            {
                float skap = k0*xr[cq0.x] + k1*xr[cq0.y] + k2*xr[cq0.z]
                           + k3*xr[cq0.w] + k4*xr[cq1.x] + k5*xr[cq1.y];
                float xv = cx.x, m = cM.x;
                float u  = cW.x + (Ksum - 2.f*skap);
                float gm = fmaf(100.f, m, -100.f) - 2.f*u;
                __stcs(outg + j0, __fdividef(1.f, 1.f + __expf(-gm*invt)));
                float x_ = 1.f - xv + EPSF;
                float ent = xv*__logf(xv + EPSF) + x_*__logf(x_);
                acc += m * (fmaf(1.f - 2.f*xv, u, -t*ent));
            }
            // element 1
            {
                float skap = k0*xr[cq1.z] + k1*xr[cq1.w] + k2*xr[cq2.x]
                           + k3*xr[cq2.y] + k4*xr[cq2.z] + k5*xr[cq2.w];
                float xv = cx.y, m = cM.y;
                float u  = cW.y + (Ksum - 2.f*skap);
                float gm = fmaf(100.f, m, -100.f) - 2.f*u;
                __stcs(outg + j0 + 1, __fdividef(1.f, 1.f + __expf(-gm*invt)));
                float x_ = 1.f - xv + EPSF;
                float ent = xv*__logf(xv + EPSF) + x_*__logf(x_);
                acc += m * (fmaf(1.f - 2.f*xv, u, -t*ent));
            }
        } else {
            // ===== full slow path (never taken for bench data, kept for rigor) =====
            float x_0 = 1.f - cx.x + EPSF;
            float x_1 = 1.f - cx.y + EPSF;
            float lx0 = __logf(x_0);
            float lx1 = __logf(x_1);
            xxs[j0]     = __fdividef(cx.x, x_0);
            xxs[j0 + 1] = __fdividef(cx.y, x_1);
            __syncthreads();

            // xxsum reduction
            float wb = wred(xxs[j0] + xxs[j0 + 1]);
            if (lane == 0) redC[tid >> 5] = wb;
            __syncthreads();
            float xxsumT = 0.f;
#pragma unroll
            for (int w = 0; w < 16; w++) xxsumT += redC[w];

            // iT: sum of 21 products (warp 0)
            if (tid < 32) {
                float spl = 0.f;
                if (tid < 21) {
                    int ka = IiT[((size_t)i * 21 + tid) * 2 + 0];
                    int kb = IiT[((size_t)i * 21 + tid) * 2 + 1];
                    spl = xxs[ka] * xxs[kb];
                }
                spl = wred(spl);
                if (tid == 0) s_spl = spl;
            }
            __syncthreads();

            float b0v = B0[0], b1v = B1[0], b2v = B2[0];
            float b1b0 = b1v - b0v, b2b1 = b2v - b1v;
            float elbrow = (b0v + xxsumT*b1v + s_spl*b2v) * __expf(rls);
            if (tid == 0) elb_extra += elbrow;

            const int4* pF = (const int4*)(IijF + (size_t)i * NN * 6);
            const int4* pT = (const int4*)(IijT + (size_t)i * NN * 30);
            int4 r0 = pF[p*3+0], r1 = pF[p*3+1], r2 = pF[p*3+2];

            // element 0
            {
                int4 u0 = pT[p*15+0], u1 = pT[p*15+1], u2 = pT[p*15+2], u3 = pT[p*15+3];
                int4 u4 = pT[p*15+4], u5 = pT[p*15+5], u6 = pT[p*15+6], u7 = pT[p*15+7];
                float locUp0 = ((xxs[cq0.x] + xxs[cq0.y]) + (xxs[cq0.z] + xxs[cq0.w]))
                             + (xxs[cq1.x] + xxs[cq1.y]);
                float skap = k0*xr[cq0.x] + k1*xr[cq0.y] + k2*xr[cq0.z]
                           + k3*xr[cq0.w] + k4*xr[cq1.x] + k5*xr[cq1.y];
                float f0 = xxs[r0.x], f1 = xxs[r0.y], f2 = xxs[r0.z],
                      f3 = xxs[r0.w], f4 = xxs[r1.x], f5 = xxs[r1.y];
                float s0 = xxs[u0.x]+xxs[u0.y]+xxs[u0.z]+xxs[u0.w]+xxs[u1.x];
                float s1 = xxs[u1.y]+xxs[u1.z]+xxs[u1.w]+xxs[u2.x]+xxs[u2.y];
                float s2 = xxs[u2.z]+xxs[u2.w]+xxs[u3.x]+xxs[u3.y]+xxs[u3.z];
                float s3 = xxs[u3.w]+xxs[u4.x]+xxs[u4.y]+xxs[u4.z]+xxs[u4.w];
                float s4 = xxs[u5.x]+xxs[u5.y]+xxs[u5.z]+xxs[u5.w]+xxs[u6.x];
                float s5 = xxs[u6.y]+xxs[u6.z]+xxs[u6.w]+xxs[u7.x]+xxs[u7.y];
                float locUp1 = f0*s0 + f1*s1 + f2*s2 + f3*s3 + f4*s4 + f5*s5;

                float xv = cx.x, m = cM.x;
                float tmp0 = __expf(rls - lx0);
                float u = cW.x + (Ksum - 2.f*skap);
                float gm = (b1b0 + b2b1*locUp0 - b2v*locUp1)*tmp0
                         + fmaf(100.f, m, -100.f) - 2.f*u;
                outg[j0] = __fdividef(1.f, 1.f + __expf(-gm*invt));
                float ent = xv*__logf(xv + EPSF) + x_0*lx0;
                acc += m * (fmaf(1.f - 2.f*xv, u, -t*ent));
            }
            // element 1
            {
                int4 u7  = pT[p*15+7];
                int4 u8  = pT[p*15+8],  u9  = pT[p*15+9],  u10 = pT[p*15+10];
                int4 u11 = pT[p*15+11], u12 = pT[p*15+12], u13 = pT[p*15+13], u14 = pT[p*15+14];
                float locUp0 = ((xxs[cq1.z] + xxs[cq1.w]) + (xxs[cq2.x] + xxs[cq2.y]))
                             + (xxs[cq2.z] + xxs[cq2.w]);
                float skap = k0*xr[cq1.z] + k1*xr[cq1.w] + k2*xr[cq2.x]
                           + k3*xr[cq2.y] + k4*xr[cq2.z] + k5*xr[cq2.w];
                float f0 = xxs[r1.z], f1 = xxs[r1.w], f2 = xxs[r2.x],
                      f3 = xxs[r2.y], f4 = xxs[r2.z], f5 = xxs[r2.w];
                float s0 = xxs[u7.z]+xxs[u7.w]+xxs[u8.x]+xxs[u8.y]+xxs[u8.z];
                float s1 = xxs[u8.w]+xxs[u9.x]+xxs[u9.y]+xxs[u9.z]+xxs[u9.w];
                float s2 = xxs[u10.x]+xxs[u10.y]+xxs[u10.z]+xxs[u10.w]+xxs[u11.x];
                float s3 = xxs[u11.y]+xxs[u11.z]+xxs[u11.w]+xxs[u12.x]+xxs[u12.y];
                float s4 = xxs[u12.z]+xxs[u12.w]+xxs[u13.x]+xxs[u13.y]+xxs[u13.z];
                float s5 = xxs[u13.w]+xxs[u14.x]+xxs[u14.y]+xxs[u14.z]+xxs[u14.w];
                float locUp1 = f0*s0 + f1*s1 + f2*s2 + f3*s3 + f4*s4 + f5*s5;

                float xv = cx.y, m = cM.y;
                float tmp0 = __expf(rls - lx1);
                float u = cW.y + (Ksum - 2.f*skap);
                float gm = (b1b0 + b2b1*locUp0 - b2v*locUp1)*tmp0
                         + fmaf(100.f, m, -100.f) - 2.f*u;
                outg[j0 + 1] = __fdividef(1.f, 1.f + __expf(-gm*invt));
                float ent = xv*__logf(xv + EPSF) + x_1*lx1;
                acc += m * (fmaf(1.f - 2.f*xv, u, -t*ent));
            }
            __syncthreads();          // xxs reuse safe for next row
        }

        // ---- rotate pipeline: publish next row's xs, shift registers ----
        if (k + 1 < ROWS_PER_BLK) {
            *(float2*)(&xs[(k + 1) & 1][j0]) = nx;
            cq0 = nq0; cq1 = nq1; cq2 = nq2;
            cW = nW; cM = nM; cx = nx; crl = nrl;
        }
    }

    // ---- single block reduction over all 4 rows ----
    float ar = wred(acc);
    if (lane == 0) redC[tid >> 5] = ar;
    __syncthreads();
    if (tid == 0) {
        float tot = 0.f;
#pragma unroll
        for (int w = 0; w < 16; w++) tot += redC[w];
        g_part[bid] = tot + elb_extra;
        __threadfence();
        unsigned int old = atomicInc(&g_ctr, GRID - 1);   // wraps to 0 after GRID incs
        s_last = (old == GRID - 1);
    }
    __syncthreads();

    // ---- last block: deterministic final sum in double ----
    if (s_last) {
        double dv = (tid < GRID) ? (double)g_part[tid] : 0.0;
        double dr = wredd(dv);
        if (lane == 0) redD[tid >> 5] = dr;
        __syncthreads();
        if (tid == 0) {
            double tt = 0.0;
#pragma unroll
            for (int w = 0; w < 16; w++) tt += redD[w];
            out[0] = (float)tt;
        }
    }
}

// ---------------------------------------------------------------------------
extern "C" void kernel_launch(void* const* d_in, const int* in_sizes, int n_in,
                              void* d_out, int out_size) {
    const float* X    = (const float*)d_in[0];
    const float* T    = (const float*)d_in[1];
    const float* C    = (const float*)d_in[2];
    const float* D    = (const float*)d_in[3];
    const float* S    = (const float*)d_in[4];
    const float* Mk   = (const float*)d_in[5];
    const float* b0   = (const float*)d_in[6];
    const float* b1   = (const float*)d_in[7];
    const float* b2   = (const float*)d_in[8];
    const float* lam  = (const float*)d_in[9];
    const float* eta  = (const float*)d_in[10];
    const float* nu   = (const float*)d_in[11];
    const float* mu   = (const float*)d_in[12];
    const float* kap  = (const float*)d_in[13];
    const int*   iij  = (const int*)d_in[14];
    const int*   iijF = (const int*)d_in[15];
    const int*   iijT = (const int*)d_in[16];
    const int*   iiT  = (const int*)d_in[17];
    float* out = (float*)d_out;

    k_prep<<<dim3(32, 32), dim3(32, 8)>>>(X, C, D, S, lam, eta, nu, mu);
    k_main<<<GRID, 512>>>(X, Mk, T, b0, b1, b2, kap,
                          iij, iijF, iijT, iiT, out);
}